// round 2
// baseline (speedup 1.0000x reference)
#include <cuda_runtime.h>

// Problem dims
#define B_   2
#define S_   2048
#define H_   1024
#define NH_  16
#define D_   64
#define MBS  (B_ * S_)                       // 4096 rows for [B*S, H] GEMMs

#define OUT_ELEMS  ((size_t)B_ * S_ * H_)            // 4,194,304
#define ATTN_ELEMS ((size_t)B_ * NH_ * S_ * S_)      // 134,217,728

// Scratch (device globals — no allocations allowed in kernel_launch).
// q/k/v/ctx stored as [B, S, N*D] row-major: column c = n*64 + d.
__device__ float g_q[OUT_ELEMS];
__device__ float g_k[OUT_ELEMS];
__device__ float g_v[OUT_ELEMS];
__device__ float g_ctx[OUT_ELEMS];
// Fallback attention buffer in case d_out only holds `out` (537 MB, zero-init bss).
__device__ float g_attn_fallback[ATTN_ELEMS];

// ---------------------------------------------------------------------------
// Kernel 1: fused q/k/v projections.
//   C[bs, c] = sum_h A[bs, h] * W[n][h][d],  c = (n<<6)|d
//   grid: (H/128, MBS/128, 3)  z selects q/k/v
// 128x128 tile, BK=16, 8x8 per thread, 256 threads.
// ---------------------------------------------------------------------------
__global__ __launch_bounds__(256) void proj_kernel(
    const float* __restrict__ inq, const float* __restrict__ ink,
    const float* __restrict__ inv,
    const float* __restrict__ Wq, const float* __restrict__ Wk,
    const float* __restrict__ Wv)
{
    const int z = blockIdx.z;
    const float* A = (z == 0) ? inq : (z == 1) ? ink : inv;
    const float* W = (z == 0) ? Wq  : (z == 1) ? Wk  : Wv;
    float* C       = (z == 0) ? g_q : (z == 1) ? g_k : g_v;

    __shared__ float As[16][128];
    __shared__ float Bs[16][128];

    const int tid = threadIdx.x;
    const int tx = tid & 15, ty = tid >> 4;
    const int m0 = blockIdx.y * 128;
    const int n0 = blockIdx.x * 128;

    float acc[8][8];
#pragma unroll
    for (int i = 0; i < 8; i++)
#pragma unroll
        for (int j = 0; j < 8; j++) acc[i][j] = 0.f;

    for (int k0 = 0; k0 < H_; k0 += 16) {
        // A tile: 128 rows x 16 k  (512 float4, 2 per thread), store transposed
#pragma unroll
        for (int i = 0; i < 2; i++) {
            int idx = tid + i * 256;
            int row = idx >> 2;
            int k4  = (idx & 3) << 2;
            float4 v = *(const float4*)(A + (size_t)(m0 + row) * H_ + k0 + k4);
            As[k4 + 0][row] = v.x; As[k4 + 1][row] = v.y;
            As[k4 + 2][row] = v.z; As[k4 + 3][row] = v.w;
        }
        // B tile: 16 k x 128 cols; W element (h, c) = W[(c>>6)*65536 + h*64 + (c&63)]
#pragma unroll
        for (int i = 0; i < 2; i++) {
            int idx = tid + i * 256;
            int kk  = idx >> 5;          // 0..15
            int c4  = (idx & 31) << 2;   // 0..124
            int cg  = n0 + c4;
            const float* src = W + ((size_t)(cg >> 6) << 16)
                                 + ((size_t)(k0 + kk) << 6) + (cg & 63);
            *(float4*)&Bs[kk][c4] = *(const float4*)src;
        }
        __syncthreads();
#pragma unroll
        for (int kk = 0; kk < 16; kk++) {
            float a[8], b[8];
            *(float4*)(a)     = *(float4*)&As[kk][ty * 8];
            *(float4*)(a + 4) = *(float4*)&As[kk][ty * 8 + 4];
            *(float4*)(b)     = *(float4*)&Bs[kk][tx * 8];
            *(float4*)(b + 4) = *(float4*)&Bs[kk][tx * 8 + 4];
#pragma unroll
            for (int i = 0; i < 8; i++)
#pragma unroll
                for (int j = 0; j < 8; j++) acc[i][j] += a[i] * b[j];
        }
        __syncthreads();
    }
#pragma unroll
    for (int i = 0; i < 8; i++) {
        size_t m = (size_t)(m0 + ty * 8 + i);
        float* dst = C + m * H_ + n0 + tx * 8;
        *(float4*)(dst)     = make_float4(acc[i][0], acc[i][1], acc[i][2], acc[i][3]);
        *(float4*)(dst + 4) = make_float4(acc[i][4], acc[i][5], acc[i][6], acc[i][7]);
    }
}

// ---------------------------------------------------------------------------
// Kernel 2: scores[z, s, t] = (q_z[s,:] . k_z[t,:]) / 8     z = b*16 + n
//   grid: (S/128, S/128, B*NH) ; K = 64
// ---------------------------------------------------------------------------
__global__ __launch_bounds__(256) void scores_kernel(float* __restrict__ attn)
{
    const int z = blockIdx.z;
    const int b = z >> 4, n = z & 15;
    const float* qb = g_q + (size_t)b * S_ * H_ + n * D_;
    const float* kb = g_k + (size_t)b * S_ * H_ + n * D_;
    float* outb = attn + (size_t)z * S_ * S_;

    __shared__ float As[16][128];
    __shared__ float Bs[16][132];   // padded: 16B-aligned rows, fewer bank conflicts

    const int tid = threadIdx.x;
    const int tx = tid & 15, ty = tid >> 4;
    const int m0 = blockIdx.y * 128;
    const int n0 = blockIdx.x * 128;

    float acc[8][8];
#pragma unroll
    for (int i = 0; i < 8; i++)
#pragma unroll
        for (int j = 0; j < 8; j++) acc[i][j] = 0.f;

    for (int k0 = 0; k0 < D_; k0 += 16) {
#pragma unroll
        for (int i = 0; i < 2; i++) {
            int idx = tid + i * 256;
            int row = idx >> 2;
            int k4  = (idx & 3) << 2;
            float4 v = *(const float4*)(qb + (size_t)(m0 + row) * H_ + k0 + k4);
            As[k4 + 0][row] = v.x; As[k4 + 1][row] = v.y;
            As[k4 + 2][row] = v.z; As[k4 + 3][row] = v.w;
        }
        // K^T tile: element (d, t) = kb[t*H + d]
#pragma unroll
        for (int i = 0; i < 2; i++) {
            int idx = tid + i * 256;
            int t  = idx >> 2;
            int d4 = (idx & 3) << 2;
            float4 v = *(const float4*)(kb + (size_t)(n0 + t) * H_ + k0 + d4);
            Bs[d4 + 0][t] = v.x; Bs[d4 + 1][t] = v.y;
            Bs[d4 + 2][t] = v.z; Bs[d4 + 3][t] = v.w;
        }
        __syncthreads();
#pragma unroll
        for (int kk = 0; kk < 16; kk++) {
            float a[8], b[8];
            *(float4*)(a)     = *(float4*)&As[kk][ty * 8];
            *(float4*)(a + 4) = *(float4*)&As[kk][ty * 8 + 4];
            *(float4*)(b)     = *(float4*)&Bs[kk][tx * 8];
            *(float4*)(b + 4) = *(float4*)&Bs[kk][tx * 8 + 4];
#pragma unroll
            for (int i = 0; i < 8; i++)
#pragma unroll
                for (int j = 0; j < 8; j++) acc[i][j] += a[i] * b[j];
        }
        __syncthreads();
    }
    const float sc = 0.125f;  // 1/sqrt(64)
#pragma unroll
    for (int i = 0; i < 8; i++) {
        size_t m = (size_t)(m0 + ty * 8 + i);
        float* dst = outb + m * S_ + n0 + tx * 8;
        *(float4*)(dst)     = make_float4(acc[i][0] * sc, acc[i][1] * sc,
                                          acc[i][2] * sc, acc[i][3] * sc);
        *(float4*)(dst + 4) = make_float4(acc[i][4] * sc, acc[i][5] * sc,
                                          acc[i][6] * sc, acc[i][7] * sc);
    }
}

// ---------------------------------------------------------------------------
// Kernel 3: in-place row softmax over attn rows of length S_.
//   grid: B*NH*S blocks of 256 threads (8 elems/thread)
// ---------------------------------------------------------------------------
__global__ __launch_bounds__(256) void softmax_kernel(float* __restrict__ attn)
{
    float* p = attn + (size_t)blockIdx.x * S_;
    const int t = threadIdx.x;

    float4 v0 = ((float4*)p)[t];
    float4 v1 = ((float4*)p)[t + 256];

    float m = fmaxf(fmaxf(fmaxf(v0.x, v0.y), fmaxf(v0.z, v0.w)),
                    fmaxf(fmaxf(v1.x, v1.y), fmaxf(v1.z, v1.w)));

    __shared__ float red[256];
    red[t] = m;
    __syncthreads();
#pragma unroll
    for (int s = 128; s > 0; s >>= 1) {
        if (t < s) red[t] = fmaxf(red[t], red[t + s]);
        __syncthreads();
    }
    m = red[0];
    __syncthreads();

    v0.x = __expf(v0.x - m); v0.y = __expf(v0.y - m);
    v0.z = __expf(v0.z - m); v0.w = __expf(v0.w - m);
    v1.x = __expf(v1.x - m); v1.y = __expf(v1.y - m);
    v1.z = __expf(v1.z - m); v1.w = __expf(v1.w - m);

    float s8 = (v0.x + v0.y + v0.z + v0.w) + (v1.x + v1.y + v1.z + v1.w);
    red[t] = s8;
    __syncthreads();
#pragma unroll
    for (int s = 128; s > 0; s >>= 1) {
        if (t < s) red[t] += red[t + s];
        __syncthreads();
    }
    const float inv = 1.f / red[0];

    v0.x *= inv; v0.y *= inv; v0.z *= inv; v0.w *= inv;
    v1.x *= inv; v1.y *= inv; v1.z *= inv; v1.w *= inv;
    ((float4*)p)[t]       = v0;
    ((float4*)p)[t + 256] = v1;
}

// ---------------------------------------------------------------------------
// Kernel 4: ctx[b, s, n*64+d] = sum_t attn[z, s, t] * v[b, t, n*64+d]
//   grid: (1, S/128, B*NH) ; tile 128x64, BK=16, 8x4 per thread
// ---------------------------------------------------------------------------
__global__ __launch_bounds__(256) void ctx_kernel(const float* __restrict__ attn)
{
    const int z = blockIdx.z;
    const int b = z >> 4, n = z & 15;
    const float* Az = attn + (size_t)z * S_ * S_;
    const float* vb = g_v + (size_t)b * S_ * H_ + n * D_;
    float* cb = g_ctx + (size_t)b * S_ * H_ + n * D_;

    __shared__ float As[16][128];
    __shared__ float Bs[16][64];

    const int tid = threadIdx.x;
    const int tx = tid & 15, ty = tid >> 4;
    const int m0 = blockIdx.y * 128;

    float acc[8][4];
#pragma unroll
    for (int i = 0; i < 8; i++)
#pragma unroll
        for (int j = 0; j < 4; j++) acc[i][j] = 0.f;

    for (int k0 = 0; k0 < S_; k0 += 16) {
#pragma unroll
        for (int i = 0; i < 2; i++) {
            int idx = tid + i * 256;
            int row = idx >> 2;
            int k4  = (idx & 3) << 2;
            float4 v = *(const float4*)(Az + (size_t)(m0 + row) * S_ + k0 + k4);
            As[k4 + 0][row] = v.x; As[k4 + 1][row] = v.y;
            As[k4 + 2][row] = v.z; As[k4 + 3][row] = v.w;
        }
        {   // B tile: 16 x 64 = 256 float4, 1 per thread
            int kk = tid >> 4;
            int d4 = (tid & 15) << 2;
            float4 v = *(const float4*)(vb + (size_t)(k0 + kk) * H_ + d4);
            *(float4*)&Bs[kk][d4] = v;
        }
        __syncthreads();
#pragma unroll
        for (int kk = 0; kk < 16; kk++) {
            float a[8], b[4];
            *(float4*)(a)     = *(float4*)&As[kk][ty * 8];
            *(float4*)(a + 4) = *(float4*)&As[kk][ty * 8 + 4];
            *(float4*)(b)     = *(float4*)&Bs[kk][tx * 4];
#pragma unroll
            for (int i = 0; i < 8; i++)
#pragma unroll
                for (int j = 0; j < 4; j++) acc[i][j] += a[i] * b[j];
        }
        __syncthreads();
    }
#pragma unroll
    for (int i = 0; i < 8; i++) {
        size_t m = (size_t)(m0 + ty * 8 + i);
        float* dst = cb + m * H_ + tx * 4;
        *(float4*)dst = make_float4(acc[i][0], acc[i][1], acc[i][2], acc[i][3]);
    }
}

// ---------------------------------------------------------------------------
// Kernel 5: out[bs, c] = sum_h ctx[bs, h] * Wo[h, c]   (standard GEMM)
//   grid: (H/128, MBS/128)
// ---------------------------------------------------------------------------
__global__ __launch_bounds__(256) void outproj_kernel(
    const float* __restrict__ Wo, float* __restrict__ out)
{
    __shared__ float As[16][128];
    __shared__ float Bs[16][128];

    const int tid = threadIdx.x;
    const int tx = tid & 15, ty = tid >> 4;
    const int m0 = blockIdx.y * 128;
    const int n0 = blockIdx.x * 128;

    float acc[8][8];
#pragma unroll
    for (int i = 0; i < 8; i++)
#pragma unroll
        for (int j = 0; j < 8; j++) acc[i][j] = 0.f;

    for (int k0 = 0; k0 < H_; k0 += 16) {
#pragma unroll
        for (int i = 0; i < 2; i++) {
            int idx = tid + i * 256;
            int row = idx >> 2;
            int k4  = (idx & 3) << 2;
            float4 v = *(const float4*)(g_ctx + (size_t)(m0 + row) * H_ + k0 + k4);
            As[k4 + 0][row] = v.x; As[k4 + 1][row] = v.y;
            As[k4 + 2][row] = v.z; As[k4 + 3][row] = v.w;
        }
#pragma unroll
        for (int i = 0; i < 2; i++) {
            int idx = tid + i * 256;
            int kk  = idx >> 5;
            int c4  = (idx & 31) << 2;
            float4 v = *(const float4*)(Wo + (size_t)(k0 + kk) * H_ + n0 + c4);
            *(float4*)&Bs[kk][c4] = v;
        }
        __syncthreads();
#pragma unroll
        for (int kk = 0; kk < 16; kk++) {
            float a[8], b[8];
            *(float4*)(a)     = *(float4*)&As[kk][ty * 8];
            *(float4*)(a + 4) = *(float4*)&As[kk][ty * 8 + 4];
            *(float4*)(b)     = *(float4*)&Bs[kk][tx * 8];
            *(float4*)(b + 4) = *(float4*)&Bs[kk][tx * 8 + 4];
#pragma unroll
            for (int i = 0; i < 8; i++)
#pragma unroll
                for (int j = 0; j < 8; j++) acc[i][j] += a[i] * b[j];
        }
        __syncthreads();
    }
#pragma unroll
    for (int i = 0; i < 8; i++) {
        size_t m = (size_t)(m0 + ty * 8 + i);
        float* dst = out + m * H_ + n0 + tx * 8;
        *(float4*)(dst)     = make_float4(acc[i][0], acc[i][1], acc[i][2], acc[i][3]);
        *(float4*)(dst + 4) = make_float4(acc[i][4], acc[i][5], acc[i][6], acc[i][7]);
    }
}

// Tiny helper: pick attention buffer device-side (no host symbol lookup needed).
__device__ float* attn_ptr_device(float* ext, int use_ext)
{
    return use_ext ? ext : g_attn_fallback;
}

// ---------------------------------------------------------------------------
extern "C" void kernel_launch(void* const* d_in, const int* in_sizes, int n_in,
                              void* d_out, int out_size)
{
    const float* q  = (const float*)d_in[0];
    const float* k  = (const float*)d_in[1];
    const float* v  = (const float*)d_in[2];
    const float* Wq = (const float*)d_in[3];
    const float* Wk = (const float*)d_in[4];
    const float* Wv = (const float*)d_in[5];
    const float* Wo = (const float*)d_in[6];
    float* out = (float*)d_out;

    // Reference returns (out, attn). If d_out holds both (concatenated in tuple
    // order), write attn directly into d_out; otherwise use the device-global
    // fallback as scratch.
    const bool attn_in_out = ((size_t)out_size >= OUT_ELEMS + ATTN_ELEMS);
    float* attn = attn_in_out ? (out + OUT_ELEMS) : nullptr;

    // For the fallback case, kernels need the real pointer. We can take the
    // address of a __device__ global only in device code, so instead launch a
    // 1-thread kernel? Simpler: when fallback is needed, pass nullptr and let
    // each kernel substitute g_attn_fallback.
    // (Implemented by checking for nullptr inside wrappers below.)

    {   // q/k/v projections
        dim3 g(H_ / 128, MBS / 128, 3);
        proj_kernel<<<g, 256>>>(q, k, v, Wq, Wk, Wv);
    }

    // scores -> attn buffer
    {
        dim3 g(S_ / 128, S_ / 128, B_ * NH_);
        if (attn)
            scores_kernel<<<g, 256>>>(attn);
        else {
            // fallback path: launch a variant writing to g_attn_fallback via a
            // device pointer obtained on device side. We reuse the same kernel
            // by passing the global's address through cudaGetSymbolAddress —
            // a pure host query, legal under graph capture (no stream work).
            void* p = nullptr;
            cudaGetSymbolAddress(&p, g_attn_fallback);
            attn = (float*)p;
            scores_kernel<<<g, 256>>>(attn);
        }
    }

    // softmax in place
    softmax_kernel<<<B_ * NH_ * S_, 256>>>(attn);

    // ctx = attn @ v
    {
        dim3 g(1, S_ / 128, B_ * NH_);
        ctx_kernel<<<g, 256>>>(attn);
    }

    // out = ctx @ Wo
    {
        dim3 g(H_ / 128, MBS / 128, 1);
        outproj_kernel<<<g, 256>>>(Wo, out);
    }
}